// round 12
// baseline (speedup 1.0000x reference)
#include <cuda_runtime.h>
#include <cuda_fp16.h>
#include <math.h>
#include <stdint.h>

#define B_DIM 1024
#define D_DIM 512
#define C_DIM 51332
#define CT_N  256
#define C_TILES 201                  // 201 * 256 = 51456
#define C_PAD (C_TILES * CT_N)

#define EPS_F   1e-3f
#define SCALE_F 64.0f

// ---------------- persistent device scratch (no runtime allocation) --------
__device__ __align__(256) float  g_invnorm[C_DIM];
__device__ __align__(256) __half g_kf16[(size_t)D_DIM * C_PAD];  // kernel fp16 [D, C_PAD]
__device__ __align__(256) __half g_ef16[B_DIM * D_DIM];          // emb fp16 [B, D]

// ---------------------------------------------------------------------------
// Kernel 1: fused fp16-convert + column sumsq + invnorm (single pass over kern)
// ---------------------------------------------------------------------------
__global__ void kprep_kernel(const float* __restrict__ kern) {
    int c = blockIdx.x * blockDim.x + threadIdx.x;
    if (c >= C_PAD) return;
    const bool valid = (c < C_DIM);
    float s0 = 0.f, s1 = 0.f, s2 = 0.f, s3 = 0.f;
#pragma unroll 4
    for (int d = 0; d < D_DIM; d += 4) {
        float v0 = valid ? kern[(size_t)(d + 0) * C_DIM + c] : 0.0f;
        float v1 = valid ? kern[(size_t)(d + 1) * C_DIM + c] : 0.0f;
        float v2 = valid ? kern[(size_t)(d + 2) * C_DIM + c] : 0.0f;
        float v3 = valid ? kern[(size_t)(d + 3) * C_DIM + c] : 0.0f;
        s0 = fmaf(v0, v0, s0);
        s1 = fmaf(v1, v1, s1);
        s2 = fmaf(v2, v2, s2);
        s3 = fmaf(v3, v3, s3);
        g_kf16[(size_t)(d + 0) * C_PAD + c] = __float2half_rn(v0);
        g_kf16[(size_t)(d + 1) * C_PAD + c] = __float2half_rn(v1);
        g_kf16[(size_t)(d + 2) * C_PAD + c] = __float2half_rn(v2);
        g_kf16[(size_t)(d + 3) * C_PAD + c] = __float2half_rn(v3);
    }
    if (valid) {
        float n = fmaxf(sqrtf((s0 + s1) + (s2 + s3)), 1e-5f);
        g_invnorm[c] = 1.0f / n;
    }
}

// ---------------------------------------------------------------------------
// Kernel 2: embeddings -> fp16
// ---------------------------------------------------------------------------
__global__ void ef16_kernel(const float* __restrict__ emb) {
    int i = (blockIdx.x * blockDim.x + threadIdx.x) * 4;
    if (i >= B_DIM * D_DIM) return;
    float4 v = *reinterpret_cast<const float4*>(emb + i);
    __half2 h01 = __floats2half2_rn(v.x, v.y);
    __half2 h23 = __floats2half2_rn(v.z, v.w);
    uint2 u;
    u.x = *reinterpret_cast<uint32_t*>(&h01);
    u.y = *reinterpret_cast<uint32_t*>(&h23);
    *reinterpret_cast<uint2*>(g_ef16 + i) = u;
}

// ---------------------------------------------------------------------------
// Kernel 3: fp16 mma.sync GEMM, 128x256 tile, BKK=32, 2-stage cp.async
// (proven R5/R10 pipeline structure; warp tile widened to 64x64)
// ---------------------------------------------------------------------------
#define BKK 32
#define AS_STRIDE 40                 // 32 halves + 8 pad
#define BS_STRIDE 264                // 256 halves + 8 pad
#define A_TILE (128 * AS_STRIDE)     // halves
#define B_TILE (BKK * BS_STRIDE)     // halves
#define SMEM_BYTES ((2 * A_TILE + 2 * B_TILE) * 2)

__device__ __forceinline__ unsigned sptr(const void* p) {
    return (unsigned)__cvta_generic_to_shared(p);
}
__device__ __forceinline__ void cp16(unsigned dst, const void* src) {
    asm volatile("cp.async.cg.shared.global [%0], [%1], 16;" :: "r"(dst), "l"(src));
}
__device__ __forceinline__ void ldsm_x4(uint32_t* r, unsigned addr) {
    asm volatile("ldmatrix.sync.aligned.m8n8.x4.shared.b16 {%0,%1,%2,%3}, [%4];"
                 : "=r"(r[0]), "=r"(r[1]), "=r"(r[2]), "=r"(r[3]) : "r"(addr));
}
__device__ __forceinline__ void ldsm_x2t(uint32_t* r, unsigned addr) {
    asm volatile("ldmatrix.sync.aligned.m8n8.x2.trans.shared.b16 {%0,%1}, [%2];"
                 : "=r"(r[0]), "=r"(r[1]) : "r"(addr));
}
__device__ __forceinline__ void mma16816(float* c, const uint32_t* a, const uint32_t* b) {
    asm volatile("mma.sync.aligned.m16n8k16.row.col.f32.f16.f16.f32 "
                 "{%0,%1,%2,%3}, {%4,%5,%6,%7}, {%8,%9}, {%0,%1,%2,%3};"
                 : "+f"(c[0]), "+f"(c[1]), "+f"(c[2]), "+f"(c[3])
                 : "r"(a[0]), "r"(a[1]), "r"(a[2]), "r"(a[3]), "r"(b[0]), "r"(b[1]));
}

__global__ __launch_bounds__(256, 1)
void gemm_f16_kernel(float* __restrict__ out)
{
    extern __shared__ __half smem[];
    __half* sA = smem;                  // 2 * A_TILE
    __half* sB = smem + 2 * A_TILE;     // 2 * B_TILE

    const int tid  = threadIdx.x;
    const int lane = tid & 31;
    const int warp = tid >> 5;
    const int wm   = warp >> 2;      // 0..1   (64-row slab)
    const int wn   = warp & 3;       // 0..3   (64-col slab)
    const int rowBase = blockIdx.x * 128;
    const int colBase = blockIdx.y * CT_N;

    float acc[4][8][4];
#pragma unroll
    for (int i = 0; i < 4; ++i)
#pragma unroll
        for (int j = 0; j < 8; ++j)
#pragma unroll
            for (int q = 0; q < 4; ++q) acc[i][j][q] = 0.0f;

    auto load_stage = [&](int ks, int buf) {
        const int k0 = ks * BKK;
        // A: 128 rows x 32 half = 512 x 16B chunks, 2 per thread
#pragma unroll
        for (int r = 0; r < 2; ++r) {
            int t   = tid + r * 256;
            int row = t >> 2;
            int ch  = t & 3;
            cp16(sptr(sA + buf * A_TILE + row * AS_STRIDE + ch * 8),
                 g_ef16 + (size_t)(rowBase + row) * D_DIM + k0 + ch * 8);
        }
        // B: 32 rows x 256 half = 1024 x 16B chunks, 4 per thread (C_PAD: no guard)
#pragma unroll
        for (int r = 0; r < 4; ++r) {
            int t   = tid + r * 256;
            int row = t >> 5;            // 0..31
            int ch  = t & 31;            // 0..31
            cp16(sptr(sB + buf * B_TILE + row * BS_STRIDE + ch * 8),
                 g_kf16 + (size_t)(k0 + row) * C_PAD + colBase + ch * 8);
        }
    };

    auto compute_stage = [&](int buf) {
        const __half* A  = sA + buf * A_TILE;
        const __half* Bt = sB + buf * B_TILE;
#pragma unroll
        for (int h = 0; h < 2; ++h) {
            const int k16 = h * 16;
            uint32_t af[4][4], bf[8][2];
#pragma unroll
            for (int mt = 0; mt < 4; ++mt) {
                int row = wm * 64 + mt * 16 + (lane & 15);
                int kc  = k16 + (lane >> 4) * 8;
                ldsm_x4(af[mt], sptr(A + row * AS_STRIDE + kc));
            }
#pragma unroll
            for (int nt = 0; nt < 8; ++nt) {
                int krow = k16 + (lane & 15);
                int nc   = wn * 64 + nt * 8;
                ldsm_x2t(bf[nt], sptr(Bt + krow * BS_STRIDE + nc));
            }
#pragma unroll
            for (int mt = 0; mt < 4; ++mt)
#pragma unroll
                for (int nt = 0; nt < 8; ++nt)
                    mma16816(acc[mt][nt], af[mt], bf[nt]);
        }
    };

    // ---- proven 2-stage pipeline: 16 stages of K=32 ----
    load_stage(0, 0);
    asm volatile("cp.async.commit_group;");
    for (int ks = 0; ks < 16; ++ks) {
        if (ks + 1 < 16) {
            load_stage(ks + 1, (ks + 1) & 1);
            asm volatile("cp.async.commit_group;");
            asm volatile("cp.async.wait_group 1;");
        } else {
            asm volatile("cp.async.wait_group 0;");
        }
        __syncthreads();
        compute_stage(ks & 1);
        __syncthreads();
    }

    // epilogue: * invnorm[c], clip, * scale  (pairs: col even, C_DIM even)
#pragma unroll
    for (int mt = 0; mt < 4; ++mt) {
#pragma unroll
        for (int nt = 0; nt < 8; ++nt) {
            int col = colBase + wn * 64 + nt * 8 + (lane & 3) * 2;
            if (col >= C_DIM) continue;
            float2 inv = *reinterpret_cast<const float2*>(g_invnorm + col);
#pragma unroll
            for (int rr = 0; rr < 2; ++rr) {
                int row = rowBase + wm * 64 + mt * 16 + (lane >> 2) + rr * 8;
                float2 v;
                v.x = fminf(fmaxf(acc[mt][nt][rr * 2 + 0] * inv.x, -1.0f + EPS_F), 1.0f - EPS_F) * SCALE_F;
                v.y = fminf(fmaxf(acc[mt][nt][rr * 2 + 1] * inv.y, -1.0f + EPS_F), 1.0f - EPS_F) * SCALE_F;
                *reinterpret_cast<float2*>(out + (size_t)row * C_DIM + col) = v;
            }
        }
    }
}

// ---------------------------------------------------------------------------
// Kernel 4: patch label entries with the AdaFace margin (exact fp32)
// ---------------------------------------------------------------------------
__global__ void patch_label_kernel(const float* __restrict__ emb,
                                   const float* __restrict__ norms,
                                   const float* __restrict__ kern,
                                   const int*   __restrict__ label,
                                   float* __restrict__ out)
{
    int warp = (blockIdx.x * blockDim.x + threadIdx.x) >> 5;
    int lane = threadIdx.x & 31;
    if (warp >= B_DIM) return;

    int col = label[warp];
    const float* erow = emb + (size_t)warp * D_DIM;

    float sum = 0.0f;
#pragma unroll
    for (int d = lane; d < D_DIM; d += 32)
        sum = fmaf(erow[d], kern[(size_t)d * C_DIM + col], sum);
#pragma unroll
    for (int o = 16; o; o >>= 1)
        sum += __shfl_xor_sync(0xffffffffu, sum, o);

    if (lane == 0) {
        float cosv = sum * g_invnorm[col];
        cosv = fminf(fmaxf(cosv, -1.0f + EPS_F), 1.0f - EPS_F);

        float sn = fminf(fmaxf(norms[warp], 1e-3f), 100.0f);
        float ms = sn / (100.0f + EPS_F) * 0.333f;        // BATCH_MEAN = 0
        ms = fminf(fmaxf(ms, -1.0f), 1.0f);

        float theta = acosf(cosv) + 0.5f * ms;            // M = 0.5
        const float PI_F = 3.14159265358979323846f;
        theta = fminf(fmaxf(theta, EPS_F), PI_F - EPS_F);
        float cm = cosf(theta) - (0.5f - 0.5f * ms);      // HEAD_B = 0.5
        out[(size_t)warp * C_DIM + col] = cm * SCALE_F;
    }
}

// ---------------------------------------------------------------------------
extern "C" void kernel_launch(void* const* d_in, const int* in_sizes, int n_in,
                              void* d_out, int out_size)
{
    const float* emb   = (const float*)d_in[0];  // [1024, 512]
    const float* norms = (const float*)d_in[1];  // [1024, 1]
    const float* kern  = (const float*)d_in[2];  // [512, 51332]
    const int*   label = (const int*)  d_in[3];  // [1024]
    float*       out   = (float*)d_out;          // [1024, 51332]

    cudaFuncSetAttribute(gemm_f16_kernel,
                         cudaFuncAttributeMaxDynamicSharedMemorySize, SMEM_BYTES);

    kprep_kernel<<<C_PAD / 256, 256>>>(kern);
    ef16_kernel<<<(B_DIM * D_DIM / 4 + 255) / 256, 256>>>(emb);

    dim3 ggrid(B_DIM / 128, C_TILES);   // row tile fastest
    gemm_f16_kernel<<<ggrid, 256, SMEM_BYTES>>>(out);

    patch_label_kernel<<<(B_DIM * 32) / 256, 256>>>(emb, norms, kern, label, out);
}